// round 11
// baseline (speedup 1.0000x reference)
#include <cuda_runtime.h>
#include <cuda_bf16.h>
#include <cstdint>

// ContrastiveCosineLoss via signed feature-Gram SYRK on warp-level bf16 MMA.
// Round 11: 128x128 CTA tiles (NT=9, 45 tiles), 32x64 warp tiles (16 indep
// accumulators/warp, MMA:LDSM=2.67), split-K=4 -> 180 CTAs in one wave,
// quarter-tile combine kernel.

#define N_SAMPLES 2048
#define D_RED     128
#define D_TOT     1152                 // 9 * 128
#define BTILE     128
#define NT9       9
#define NTIL      45                   // 9*10/2
#define NSPLIT    4
#define KSPLIT    (N_SAMPLES / NSPLIT) // 512
#define CHUNK     64
#define NCHUNK_S  (KSPLIT / CHUNK)     // 8
#define PITCH     136                  // bf16 per SMEM row (272B: LDSM.T bank-safe)
#define STAGES    3
#define SLAB      (CHUNK * PITCH * 2)  // 17408 B per operand slab
#define GSMEM     (STAGES * 2 * SLAB)  // 104448 B dynamic smem
#define NPART     (NTIL * 4)           // 180 combine work items

__device__ __align__(4096) __nv_bfloat16 g_Yb[N_SAMPLES * D_TOT];
__device__ __align__(4096) float g_G[NSPLIT * NTIL * BTILE * BTILE];  // 11.8 MB
__device__ float g_part[NPART];
__device__ unsigned int g_count;       // zero-init; self-resetting

// ---------------------------------------------------------------------------
__device__ __forceinline__ uint32_t smem_u32(const void* p) {
    uint32_t a;
    asm("{ .reg .u64 t; cvta.to.shared.u64 t, %1; cvt.u32.u64 %0, t; }" : "=r"(a) : "l"(p));
    return a;
}
__device__ __forceinline__ void cp16(uint32_t sdst, const void* g) {
    asm volatile("cp.async.cg.shared.global [%0], [%1], 16;" :: "r"(sdst), "l"(g) : "memory");
}
__device__ __forceinline__ void ldsm_x4_t(uint32_t* r, uint32_t addr) {
    asm volatile("ldmatrix.sync.aligned.m8n8.x4.trans.shared.b16 {%0,%1,%2,%3}, [%4];"
                 : "=r"(r[0]), "=r"(r[1]), "=r"(r[2]), "=r"(r[3]) : "r"(addr));
}
__device__ __forceinline__ void mma_bf16(float* c, const uint32_t* a, uint32_t b0, uint32_t b1) {
    asm volatile(
        "mma.sync.aligned.m16n8k16.row.col.f32.bf16.bf16.f32 "
        "{%0,%1,%2,%3}, {%4,%5,%6,%7}, {%8,%9}, {%0,%1,%2,%3};"
        : "+f"(c[0]), "+f"(c[1]), "+f"(c[2]), "+f"(c[3])
        : "r"(a[0]), "r"(a[1]), "r"(a[2]), "r"(a[3]), "r"(b0), "r"(b1));
}

// ---------------------------------------------------------------------------
// Kernel 1: row-normalize -> bf16 row-major. One warp per sample row, MLP 8.
// ---------------------------------------------------------------------------
__global__ void __launch_bounds__(256) normalize_kernel(const float* __restrict__ red,
                                                        const float* __restrict__ full) {
    int t = threadIdx.x, lane = t & 31, wid = t >> 5;
    int row = blockIdx.x * 8 + wid;

    const float4* f4 = (const float4*)(full + (size_t)row * 1024);
    const float4* r4 = (const float4*)(red  + (size_t)row * D_RED);

    float4 fv[8];
    #pragma unroll
    for (int j = 0; j < 8; j++) fv[j] = f4[lane + 32 * j];
    float4 rv = r4[lane];

    float sf = 0.f;
    #pragma unroll
    for (int j = 0; j < 8; j++)
        sf += fv[j].x * fv[j].x + fv[j].y * fv[j].y + fv[j].z * fv[j].z + fv[j].w * fv[j].w;
    float sr = rv.x * rv.x + rv.y * rv.y + rv.z * rv.z + rv.w * rv.w;

    #pragma unroll
    for (int o = 16; o > 0; o >>= 1) {
        sf += __shfl_xor_sync(0xFFFFFFFFu, sf, o);
        sr += __shfl_xor_sync(0xFFFFFFFFu, sr, o);
    }
    float iff = 1.f / fmaxf(sqrtf(sf), 1e-8f);
    float ir  = 1.f / fmaxf(sqrtf(sr), 1e-8f);

    {
        __nv_bfloat162 h0 = __floats2bfloat162_rn(rv.x * ir, rv.y * ir);
        __nv_bfloat162 h1 = __floats2bfloat162_rn(rv.z * ir, rv.w * ir);
        ((uint2*)(g_Yb + (size_t)row * D_TOT))[lane] =
            make_uint2(*(uint32_t*)&h0, *(uint32_t*)&h1);
    }
    uint2* dst = (uint2*)(g_Yb + (size_t)row * D_TOT + D_RED);
    #pragma unroll
    for (int j = 0; j < 8; j++) {
        __nv_bfloat162 h0 = __floats2bfloat162_rn(fv[j].x * iff, fv[j].y * iff);
        __nv_bfloat162 h1 = __floats2bfloat162_rn(fv[j].z * iff, fv[j].w * iff);
        dst[lane + 32 * j] = make_uint2(*(uint32_t*)&h0, *(uint32_t*)&h1);
    }
}

// ---------------------------------------------------------------------------
// Kernel 2: bf16 warp-MMA partial SYRK, 128x128 tile, split-K=4.
// 8 warps = 4 (m) x 2 (n), warp tile 32x64. Writes partial Gram to g_G.
// grid = (NTIL, NSPLIT), 256 threads.
// ---------------------------------------------------------------------------
__global__ void __launch_bounds__(256, 2) gram_kernel() {
    extern __shared__ __align__(16) char dyn[];
    int t = threadIdx.x, lane = t & 31, wid = t >> 5;

    int blk = blockIdx.x, split = blockIdx.y;
    int a = 0, rem = blk, rl = NT9;
    while (rem >= rl) { rem -= rl; a++; rl--; }
    int b2 = a + rem;
    bool diag = (a == b2);

    // ---- cp.async addressing: 64 rows x 16 segs(16B) per slab ----
    int row0 = t >> 4;             // 0..15
    int seg  = (t & 15) * 8;       // bf16 col of 16B segment
    uint32_t sA0 = smem_u32(dyn) + (uint32_t)(row0 * PITCH + seg) * 2;
    uint32_t sB0 = sA0 + SLAB;
    const uint32_t rowStep = 16 * PITCH * 2;
    const __nv_bfloat16* gA0 = g_Yb + (size_t)(split * KSPLIT + row0) * D_TOT + a  * BTILE + seg;
    const __nv_bfloat16* gB0 = g_Yb + (size_t)(split * KSPLIT + row0) * D_TOT + b2 * BTILE + seg;
    const size_t gRow = (size_t)16 * D_TOT;
    const size_t gChunk = (size_t)CHUNK * D_TOT;

    auto load_chunk = [&](int s, int c) {
        uint32_t so = (uint32_t)(s * 2 * SLAB);
        const __nv_bfloat16* ga = gA0 + c * gChunk;
        #pragma unroll
        for (int j = 0; j < 4; j++)
            cp16(sA0 + so + j * rowStep, ga + j * gRow);
        if (!diag) {
            const __nv_bfloat16* gb = gB0 + c * gChunk;
            #pragma unroll
            for (int j = 0; j < 4; j++)
                cp16(sB0 + so + j * rowStep, gb + j * gRow);
        }
    };

    // ---- warp tiling: 4 m-warps x 2 n-warps, warp tile 32x64 ----
    int m0 = (wid & 3) * 32;
    int n0 = (wid >> 2) * 64;
    int lrow = (lane & 7) + ((lane >> 4) & 1) * 8;
    int lcol = ((lane >> 3) & 1) * 8;
    uint32_t base = smem_u32(dyn);
    uint32_t aA = base + (uint32_t)(lrow * PITCH + m0 + lcol) * 2;
    uint32_t aB = base + (diag ? 0u : (uint32_t)SLAB)
                       + (uint32_t)(lrow * PITCH + n0 + lcol) * 2;
    const uint32_t kStep = 16 * PITCH * 2;

    float acc[2][8][4] = {};

    load_chunk(0, 0);
    asm volatile("cp.async.commit_group;" ::: "memory");
    load_chunk(1, 1);
    asm volatile("cp.async.commit_group;" ::: "memory");

    int s = 0;
    for (int c = 0; c < NCHUNK_S; c++) {
        asm volatile("cp.async.wait_group 1;" ::: "memory");
        __syncthreads();

        if (c + 2 < NCHUNK_S) {
            int s2 = s + 2; if (s2 >= STAGES) s2 -= STAGES;
            load_chunk(s2, c + 2);
        }
        asm volatile("cp.async.commit_group;" ::: "memory");

        uint32_t so = (uint32_t)(s * 2 * SLAB);
        #pragma unroll
        for (int ks = 0; ks < 4; ks++) {
            uint32_t ko = so + ks * kStep;
            uint32_t af[2][4], bf[4][4];
            ldsm_x4_t(af[0], aA + ko);
            ldsm_x4_t(af[1], aA + ko + 32);            // +16 m cols
            #pragma unroll
            for (int q = 0; q < 4; q++)
                ldsm_x4_t(bf[q], aB + ko + q * 32);    // +16 n cols each
            // bf[q]: r0=(K0,N0..7) r1=(K0,N8..15) r2=(K8,N0..7) r3=(K8,N8..15)
            #pragma unroll
            for (int mi = 0; mi < 2; mi++)
                #pragma unroll
                for (int nj = 0; nj < 8; nj++) {
                    int q = nj >> 1, sub = nj & 1;
                    mma_bf16(acc[mi][nj], af[mi], bf[q][sub], bf[q][sub + 2]);
                }
        }
        if (++s >= STAGES) s -= STAGES;
    }

    // ---- write 128x128 partial tile (row-major) ----
    {
        float2* G2 = (float2*)(g_G + ((size_t)(split * NTIL + blk)) * (BTILE * BTILE));
        int grow = lane >> 2;            // 0..7
        int gc2  = (lane & 3);           // float2 col within n8 group
        #pragma unroll
        for (int mi = 0; mi < 2; mi++)
            #pragma unroll
            for (int nj = 0; nj < 8; nj++) {
                int r = m0 + mi * 16 + grow;
                int cidx = (n0 + nj * 8) / 2 + gc2;
                G2[(size_t)r * 64 + cidx] =
                    make_float2(acc[mi][nj][0], acc[mi][nj][1]);
                G2[(size_t)(r + 8) * 64 + cidx] =
                    make_float2(acc[mi][nj][2], acc[mi][nj][3]);
            }
    }
}

// ---------------------------------------------------------------------------
// Kernel 3: combine splits (fixed order), square, signed reduce, finalize.
// grid = 180 (45 tiles x 4 row-quarters), 256 threads.
// ---------------------------------------------------------------------------
__global__ void __launch_bounds__(256) combine_kernel(float* __restrict__ out) {
    __shared__ float sred[8];
    __shared__ unsigned int s_last;
    int t = threadIdx.x, lane = t & 31, wid = t >> 5;
    int blk = blockIdx.x;
    int tile = blk >> 2, q = blk & 3;

    int a = 0, rem = tile, rl = NT9;
    while (rem >= rl) { rem -= rl; a++; rl--; }
    int b2 = a + rem;

    const float4* G4 = (const float4*)g_G;
    size_t baseIdx = (size_t)tile * 4096 + (size_t)q * 1024;  // float4 units

    float sum = 0.f;
    #pragma unroll
    for (int j = 0; j < 4; j++) {
        size_t idx = baseIdx + j * 256 + t;
        float x = 0.f, y = 0.f, z = 0.f, w = 0.f;
        #pragma unroll
        for (int sp = 0; sp < NSPLIT; sp++) {   // fixed order: deterministic
            float4 u = G4[(size_t)sp * NTIL * 4096 + idx];
            x += u.x; y += u.y; z += u.z; w += u.w;
        }
        sum += x * x + y * y + z * z + w * w;
    }
    #pragma unroll
    for (int o = 16; o > 0; o >>= 1)
        sum += __shfl_xor_sync(0xFFFFFFFFu, sum, o);
    if (lane == 0) sred[wid] = sum;
    __syncthreads();
    if (t == 0) {
        float tot = 0.f;
        #pragma unroll
        for (int i = 0; i < 8; i++) tot += sred[i];
        float sp = ((a == 0) != (b2 == 0)) ? -1.f : 1.f;
        float w  = sp * ((a == b2) ? 1.f : 2.f);
        g_part[blk] = w * tot;
        __threadfence();
        s_last = (atomicAdd(&g_count, 1u) == NPART - 1);
    }
    __syncthreads();

    if (s_last) {
        __threadfence();
        __shared__ float fs[256];
        fs[t] = (t < NPART) ? g_part[t] : 0.f;
        __syncthreads();
        #pragma unroll
        for (int o = 128; o > 0; o >>= 1) {
            if (t < o) fs[t] += fs[t + o];
            __syncthreads();
        }
        if (t == 0) {
            out[0] = fs[0] / ((float)N_SAMPLES * (float)(N_SAMPLES - 1));
            g_count = 0;
        }
    }
}

// ---------------------------------------------------------------------------
extern "C" void kernel_launch(void* const* d_in, const int* in_sizes, int n_in,
                              void* d_out, int out_size) {
    const float* red;
    const float* full;
    if (in_sizes[0] == N_SAMPLES * D_RED) {
        red  = (const float*)d_in[0];
        full = (const float*)d_in[1];
    } else {
        red  = (const float*)d_in[1];
        full = (const float*)d_in[0];
    }

    static int attr_done = 0;
    if (!attr_done) {
        cudaFuncSetAttribute(gram_kernel, cudaFuncAttributeMaxDynamicSharedMemorySize,
                             GSMEM);
        attr_done = 1;
    }

    normalize_kernel<<<N_SAMPLES / 8, 256>>>(red, full);
    gram_kernel<<<dim3(NTIL, NSPLIT), 256, GSMEM>>>();
    combine_kernel<<<NPART, 256>>>((float*)d_out);
}

// round 12
// speedup vs baseline: 1.0625x; 1.0625x over previous
#include <cuda_runtime.h>
#include <cuda_bf16.h>
#include <cstdint>

// ContrastiveCosineLoss via signed feature-Gram SYRK on warp-level bf16 MMA.
// Round 12: ONE fused kernel. 342 co-resident CTAs (171 tiles x split-K 2):
// phase A normalizes rows (warp-per-row) and publishes 64-row-group readiness
// flags; phase B is the R8 gram pipeline gated per-chunk on those flags
// (producer/consumer overlap); phase C decoupled combine + last-CTA finalize.

#define N_SAMPLES 2048
#define D_RED     128
#define D_TOT     1152                 // 18 * 64
#define TILE      64
#define NT        18
#define NTILES    171
#define NSPLIT    2
#define KSPLIT    (N_SAMPLES / NSPLIT) // 1024
#define CHUNK     64
#define NCHUNK_S  (KSPLIT / CHUNK)     // 16
#define NGROUP    (N_SAMPLES / CHUNK)  // 32 row groups
#define PITCH     72                   // bf16 per SMEM row (144B: LDSM.T bank-safe)
#define STAGES    3
#define SLABB     (CHUNK * PITCH * 2)  // 9216 B per operand slab
#define GSMEM     (STAGES * 2 * SLABB) // 55296 B dynamic smem
#define GRID      (NTILES * NSPLIT)    // 342 CTAs, all co-resident

__device__ __align__(4096) __nv_bfloat16 g_Yb[N_SAMPLES * D_TOT];
__device__ __align__(4096) float g_G[NSPLIT * NTILES * TILE * TILE];
__device__ float g_part[NTILES];
__device__ unsigned int g_row_count[NGROUP];   // zero-init; reset by finalize
__device__ unsigned int g_tile_count[NTILES];  // zero-init; reset by combiner
__device__ unsigned int g_count;               // zero-init; reset by finalize

// ---------------------------------------------------------------------------
__device__ __forceinline__ uint32_t smem_u32(const void* p) {
    uint32_t a;
    asm("{ .reg .u64 t; cvta.to.shared.u64 t, %1; cvt.u32.u64 %0, t; }" : "=r"(a) : "l"(p));
    return a;
}
__device__ __forceinline__ void cp16(uint32_t sdst, const void* g) {
    asm volatile("cp.async.cg.shared.global [%0], [%1], 16;" :: "r"(sdst), "l"(g) : "memory");
}
__device__ __forceinline__ void ldsm_x4_t(uint32_t* r, uint32_t addr) {
    asm volatile("ldmatrix.sync.aligned.m8n8.x4.trans.shared.b16 {%0,%1,%2,%3}, [%4];"
                 : "=r"(r[0]), "=r"(r[1]), "=r"(r[2]), "=r"(r[3]) : "r"(addr));
}
__device__ __forceinline__ void mma_bf16(float* c, const uint32_t* a, uint32_t b0, uint32_t b1) {
    asm volatile(
        "mma.sync.aligned.m16n8k16.row.col.f32.bf16.bf16.f32 "
        "{%0,%1,%2,%3}, {%4,%5,%6,%7}, {%8,%9}, {%0,%1,%2,%3};"
        : "+f"(c[0]), "+f"(c[1]), "+f"(c[2]), "+f"(c[3])
        : "r"(a[0]), "r"(a[1]), "r"(a[2]), "r"(a[3]), "r"(b0), "r"(b1));
}
__device__ __forceinline__ unsigned int ld_acq(const unsigned int* p) {
    unsigned int v;
    asm volatile("ld.acquire.gpu.u32 %0, [%1];" : "=r"(v) : "l"(p) : "memory");
    return v;
}

// ---------------------------------------------------------------------------
__global__ void __launch_bounds__(256, 3) fused_kernel(const float* __restrict__ red,
                                                       const float* __restrict__ full,
                                                       float* __restrict__ out) {
    extern __shared__ __align__(16) char dyn[];
    __shared__ float sred[8];
    __shared__ unsigned int s_comb, s_last;

    int t = threadIdx.x, lane = t & 31, wid = t >> 5;

    // ============ Phase A: normalize (one warp per sample row) ============
    int gw = blockIdx.x * 8 + wid;      // 342*8 = 2736 warps; first 2048 work
    if (gw < N_SAMPLES) {
        int row = gw;
        const float4* f4 = (const float4*)(full + (size_t)row * 1024);
        const float4* r4 = (const float4*)(red  + (size_t)row * D_RED);

        float4 fv[8];
        #pragma unroll
        for (int j = 0; j < 8; j++) fv[j] = f4[lane + 32 * j];
        float4 rv = r4[lane];

        float sf = 0.f;
        #pragma unroll
        for (int j = 0; j < 8; j++)
            sf += fv[j].x * fv[j].x + fv[j].y * fv[j].y + fv[j].z * fv[j].z + fv[j].w * fv[j].w;
        float sr = rv.x * rv.x + rv.y * rv.y + rv.z * rv.z + rv.w * rv.w;

        #pragma unroll
        for (int o = 16; o > 0; o >>= 1) {
            sf += __shfl_xor_sync(0xFFFFFFFFu, sf, o);
            sr += __shfl_xor_sync(0xFFFFFFFFu, sr, o);
        }
        float iff = 1.f / fmaxf(sqrtf(sf), 1e-8f);
        float ir  = 1.f / fmaxf(sqrtf(sr), 1e-8f);

        {
            __nv_bfloat162 h0 = __floats2bfloat162_rn(rv.x * ir, rv.y * ir);
            __nv_bfloat162 h1 = __floats2bfloat162_rn(rv.z * ir, rv.w * ir);
            ((uint2*)(g_Yb + (size_t)row * D_TOT))[lane] =
                make_uint2(*(uint32_t*)&h0, *(uint32_t*)&h1);
        }
        uint2* dst = (uint2*)(g_Yb + (size_t)row * D_TOT + D_RED);
        #pragma unroll
        for (int j = 0; j < 8; j++) {
            __nv_bfloat162 h0 = __floats2bfloat162_rn(fv[j].x * iff, fv[j].y * iff);
            __nv_bfloat162 h1 = __floats2bfloat162_rn(fv[j].z * iff, fv[j].w * iff);
            dst[lane + 32 * j] = make_uint2(*(uint32_t*)&h0, *(uint32_t*)&h1);
        }
        __threadfence();                 // release row data
        if (lane == 0) atomicAdd(&g_row_count[row >> 6], 1u);
    }

    // ============ Phase B: gram tile (split-K=2, flag-gated chunks) ========
    int blk = blockIdx.x >> 1, split = blockIdx.x & 1;
    int a = 0, rem = blk, rl = NT;
    while (rem >= rl) { rem -= rl; a++; rl--; }
    int b2 = a + rem;

    // hoisted cp.async addressing
    int lrowg = t >> 3;
    int lv    = (t & 7) * 8;
    uint32_t sA0 = smem_u32(dyn) + (uint32_t)(lrowg * PITCH + lv) * 2;
    uint32_t sB0 = sA0 + SLABB;
    const uint32_t rowStep = 32 * PITCH * 2;
    const __nv_bfloat16* gA0 = g_Yb + (size_t)(split * KSPLIT + lrowg) * D_TOT + a * TILE + lv;
    const __nv_bfloat16* gB0 = g_Yb + (size_t)(split * KSPLIT + lrowg) * D_TOT + b2 * TILE + lv;
    const size_t gRow = (size_t)32 * D_TOT;
    const size_t gChunk = (size_t)CHUNK * D_TOT;

    auto load_chunk = [&](int s, int c) {
        uint32_t so = (uint32_t)(s * 2 * SLABB);
        const __nv_bfloat16* ga = gA0 + c * gChunk;
        const __nv_bfloat16* gb = gB0 + c * gChunk;
        cp16(sA0 + so,           ga);
        cp16(sA0 + so + rowStep, ga + gRow);
        cp16(sB0 + so,           gb);
        cp16(sB0 + so + rowStep, gb + gRow);
    };

    // warp tiling: 2x2 quadrants x 2 k-halves
    int wq = wid & 3, kh = wid >> 2;
    int m0 = (wq & 1) * 32;
    int n0 = (wq >> 1) * 32;
    int lrow = (lane & 7) + ((lane >> 4) & 1) * 8;
    int lcol = ((lane >> 3) & 1) * 8;
    uint32_t base = smem_u32(dyn);
    uint32_t aA = base + (uint32_t)((kh * 32 + lrow) * PITCH + m0 + lcol) * 2;
    uint32_t aB = base + SLABB + (uint32_t)((kh * 32 + lrow) * PITCH + n0 + lcol) * 2;
    const uint32_t kStep = 16 * PITCH * 2;

    float acc[2][4][4] = {};

    const int gbase = split * NCHUNK_S;      // absolute row-group of chunk 0
    if (t == 0) {                            // wait for first two chunks
        while (ld_acq(&g_row_count[gbase + 0]) < 64u) {}
        while (ld_acq(&g_row_count[gbase + 1]) < 64u) {}
    }
    __syncthreads();

    load_chunk(0, 0);
    asm volatile("cp.async.commit_group;" ::: "memory");
    load_chunk(1, 1);
    asm volatile("cp.async.commit_group;" ::: "memory");

    int s = 0;
    for (int c = 0; c < NCHUNK_S; c++) {
        asm volatile("cp.async.wait_group 1;" ::: "memory");
        if (t == 0 && c + 2 < NCHUNK_S) {
            while (ld_acq(&g_row_count[gbase + c + 2]) < 64u) {}
        }
        __syncthreads();

        if (c + 2 < NCHUNK_S) {
            int s2 = s + 2; if (s2 >= STAGES) s2 -= STAGES;
            load_chunk(s2, c + 2);
        }
        asm volatile("cp.async.commit_group;" ::: "memory");

        uint32_t so = (uint32_t)(s * 2 * SLABB);
        uint32_t af[2][2][4], bf[2][2][4];
        #pragma unroll
        for (int ks = 0; ks < 2; ks++) {
            uint32_t ko = so + ks * kStep;
            ldsm_x4_t(af[ks][0], aA + ko);
            ldsm_x4_t(af[ks][1], aA + ko + 32);
            ldsm_x4_t(bf[ks][0], aB + ko);
            ldsm_x4_t(bf[ks][1], aB + ko + 32);
        }
        #pragma unroll
        for (int ks = 0; ks < 2; ks++)
            #pragma unroll
            for (int mi = 0; mi < 2; mi++) {
                mma_bf16(acc[mi][0], af[ks][mi], bf[ks][0][0], bf[ks][0][2]);
                mma_bf16(acc[mi][1], af[ks][mi], bf[ks][0][1], bf[ks][0][3]);
                mma_bf16(acc[mi][2], af[ks][mi], bf[ks][1][0], bf[ks][1][2]);
                mma_bf16(acc[mi][3], af[ks][mi], bf[ks][1][1], bf[ks][1][3]);
            }
        if (++s >= STAGES) s -= STAGES;
    }

    // merge k-halves via SMEM, write partial Gram
    __syncthreads();
    float4* M4 = (float4*)dyn;
    int tt = wq * 32 + lane;
    if (kh == 1) {
        #pragma unroll
        for (int mi = 0; mi < 2; mi++)
            #pragma unroll
            for (int ni = 0; ni < 4; ni++)
                M4[(mi * 4 + ni) * 128 + tt] =
                    make_float4(acc[mi][ni][0], acc[mi][ni][1],
                                acc[mi][ni][2], acc[mi][ni][3]);
    }
    __syncthreads();
    if (kh == 0) {
        float4* G4 = (float4*)g_G + ((size_t)(split * NTILES + blk)) * 1024;
        #pragma unroll
        for (int mi = 0; mi < 2; mi++)
            #pragma unroll
            for (int ni = 0; ni < 4; ni++) {
                int f = mi * 4 + ni;
                float4 v = M4[f * 128 + tt];
                G4[f * 128 + tt] = make_float4(acc[mi][ni][0] + v.x,
                                               acc[mi][ni][1] + v.y,
                                               acc[mi][ni][2] + v.z,
                                               acc[mi][ni][3] + v.w);
            }
    }

    // ============ Phase C: decoupled per-tile combine + finalize ===========
    __syncthreads();
    if (t == 0) {
        __threadfence();
        s_comb = (atomicAdd(&g_tile_count[blk], 1u) == NSPLIT - 1);
    }
    __syncthreads();
    if (!s_comb) return;

    __threadfence();   // acquire sibling's partial
    {
        const float4* G4 = (const float4*)g_G;
        float sum = 0.f;
        #pragma unroll
        for (int f = 0; f < 4; f++) {
            size_t idx = (size_t)blk * 1024 + f * 256 + t;
            float x = 0.f, y = 0.f, z = 0.f, w = 0.f;
            #pragma unroll
            for (int sp = 0; sp < NSPLIT; sp++) {   // fixed order: deterministic
                float4 u = G4[(size_t)sp * NTILES * 1024 + idx];
                x += u.x; y += u.y; z += u.z; w += u.w;
            }
            sum += x * x + y * y + z * z + w * w;
        }
        #pragma unroll
        for (int o = 16; o > 0; o >>= 1)
            sum += __shfl_xor_sync(0xFFFFFFFFu, sum, o);
        if (lane == 0) sred[wid] = sum;
    }
    __syncthreads();
    if (t == 0) {
        float tot = 0.f;
        #pragma unroll
        for (int i = 0; i < 8; i++) tot += sred[i];
        float sp = ((a < 2) != (b2 < 2)) ? -1.f : 1.f;
        float w  = sp * ((a == b2) ? 1.f : 2.f);
        g_part[blk] = w * tot;
        g_tile_count[blk] = 0;     // reset for next graph replay
        __threadfence();
        s_last = (atomicAdd(&g_count, 1u) == NTILES - 1);
    }
    __syncthreads();

    if (s_last) {
        __threadfence();
        __shared__ float fs[256];
        fs[t] = (t < NTILES) ? g_part[t] : 0.f;
        if (t < NGROUP) g_row_count[t] = 0;   // reset row flags for replay
        __syncthreads();
        #pragma unroll
        for (int o = 128; o > 0; o >>= 1) {
            if (t < o) fs[t] += fs[t + o];
            __syncthreads();
        }
        if (t == 0) {
            out[0] = fs[0] / ((float)N_SAMPLES * (float)(N_SAMPLES - 1));
            g_count = 0;           // reset for next graph replay
        }
    }
}

// ---------------------------------------------------------------------------
extern "C" void kernel_launch(void* const* d_in, const int* in_sizes, int n_in,
                              void* d_out, int out_size) {
    const float* red;
    const float* full;
    if (in_sizes[0] == N_SAMPLES * D_RED) {
        red  = (const float*)d_in[0];
        full = (const float*)d_in[1];
    } else {
        red  = (const float*)d_in[1];
        full = (const float*)d_in[0];
    }

    static int attr_done = 0;
    if (!attr_done) {
        cudaFuncSetAttribute(fused_kernel, cudaFuncAttributeMaxDynamicSharedMemorySize,
                             GSMEM);
        attr_done = 1;
    }

    fused_kernel<<<GRID, 256, GSMEM>>>(red, full, (float*)d_out);
}

// round 13
// speedup vs baseline: 1.2360x; 1.1633x over previous
#include <cuda_runtime.h>
#include <cuda_bf16.h>
#include <cstdint>

// ContrastiveCosineLoss via signed feature-Gram SYRK on warp-level bf16 MMA.
// Round 13: R8 (best) + 4-stage cp.async pipeline (prefetch distance 3,
// wait_group 2) to add latency slack per chunk. Everything else identical.

#define N_SAMPLES 2048
#define D_RED     128
#define D_TOT     1152                 // 18 * 64
#define TILE      64
#define NT        18
#define NTILES    171
#define NSPLIT    4
#define KSPLIT    (N_SAMPLES / NSPLIT) // 512
#define CHUNK     64
#define NCHUNK_S  (KSPLIT / CHUNK)     // 8
#define PITCH     72                   // bf16 per SMEM row (144B: LDSM.T bank-safe)
#define STAGES    4
#define SLABB     (CHUNK * PITCH * 2)  // 9216 B per operand slab
#define GSMEM     (STAGES * 2 * SLABB) // 73728 B dynamic smem (3 CTAs/SM)

__device__ __align__(4096) __nv_bfloat16 g_Yb[N_SAMPLES * D_TOT];
__device__ __align__(4096) float g_G[NSPLIT * NTILES * TILE * TILE];
__device__ float g_part[NTILES];
__device__ unsigned int g_tile_count[NTILES];  // zero-init; self-resetting
__device__ unsigned int g_count;               // zero-init; self-resetting

// ---------------------------------------------------------------------------
__device__ __forceinline__ uint32_t smem_u32(const void* p) {
    uint32_t a;
    asm("{ .reg .u64 t; cvta.to.shared.u64 t, %1; cvt.u32.u64 %0, t; }" : "=r"(a) : "l"(p));
    return a;
}
__device__ __forceinline__ void cp16(uint32_t sdst, const void* g) {
    asm volatile("cp.async.cg.shared.global [%0], [%1], 16;" :: "r"(sdst), "l"(g) : "memory");
}
__device__ __forceinline__ void ldsm_x4_t(uint32_t* r, uint32_t addr) {
    asm volatile("ldmatrix.sync.aligned.m8n8.x4.trans.shared.b16 {%0,%1,%2,%3}, [%4];"
                 : "=r"(r[0]), "=r"(r[1]), "=r"(r[2]), "=r"(r[3]) : "r"(addr));
}
__device__ __forceinline__ void mma_bf16(float* c, const uint32_t* a, uint32_t b0, uint32_t b1) {
    asm volatile(
        "mma.sync.aligned.m16n8k16.row.col.f32.bf16.bf16.f32 "
        "{%0,%1,%2,%3}, {%4,%5,%6,%7}, {%8,%9}, {%0,%1,%2,%3};"
        : "+f"(c[0]), "+f"(c[1]), "+f"(c[2]), "+f"(c[3])
        : "r"(a[0]), "r"(a[1]), "r"(a[2]), "r"(a[3]), "r"(b0), "r"(b1));
}

// ---------------------------------------------------------------------------
// Kernel 1: row-normalize -> bf16 row-major. One warp per sample row, MLP 8.
// ---------------------------------------------------------------------------
__global__ void __launch_bounds__(256) normalize_kernel(const float* __restrict__ red,
                                                        const float* __restrict__ full) {
    int t = threadIdx.x, lane = t & 31, wid = t >> 5;
    int row = blockIdx.x * 8 + wid;

    const float4* f4 = (const float4*)(full + (size_t)row * 1024);
    const float4* r4 = (const float4*)(red  + (size_t)row * D_RED);

    float4 fv[8];
    #pragma unroll
    for (int j = 0; j < 8; j++) fv[j] = f4[lane + 32 * j];
    float4 rv = r4[lane];

    float sf = 0.f;
    #pragma unroll
    for (int j = 0; j < 8; j++)
        sf += fv[j].x * fv[j].x + fv[j].y * fv[j].y + fv[j].z * fv[j].z + fv[j].w * fv[j].w;
    float sr = rv.x * rv.x + rv.y * rv.y + rv.z * rv.z + rv.w * rv.w;

    #pragma unroll
    for (int o = 16; o > 0; o >>= 1) {
        sf += __shfl_xor_sync(0xFFFFFFFFu, sf, o);
        sr += __shfl_xor_sync(0xFFFFFFFFu, sr, o);
    }
    float iff = 1.f / fmaxf(sqrtf(sf), 1e-8f);
    float ir  = 1.f / fmaxf(sqrtf(sr), 1e-8f);

    {
        __nv_bfloat162 h0 = __floats2bfloat162_rn(rv.x * ir, rv.y * ir);
        __nv_bfloat162 h1 = __floats2bfloat162_rn(rv.z * ir, rv.w * ir);
        ((uint2*)(g_Yb + (size_t)row * D_TOT))[lane] =
            make_uint2(*(uint32_t*)&h0, *(uint32_t*)&h1);
    }
    uint2* dst = (uint2*)(g_Yb + (size_t)row * D_TOT + D_RED);
    #pragma unroll
    for (int j = 0; j < 8; j++) {
        __nv_bfloat162 h0 = __floats2bfloat162_rn(fv[j].x * iff, fv[j].y * iff);
        __nv_bfloat162 h1 = __floats2bfloat162_rn(fv[j].z * iff, fv[j].w * iff);
        dst[lane + 32 * j] = make_uint2(*(uint32_t*)&h0, *(uint32_t*)&h1);
    }
}

// ---------------------------------------------------------------------------
// Kernel 2: bf16 warp-MMA partial SYRK (split-K=4) + decoupled per-tile
// combine + global finalize. grid = (NTILES, NSPLIT), 256 threads.
// ---------------------------------------------------------------------------
__global__ void __launch_bounds__(256, 3) gram_kernel(float* __restrict__ out) {
    extern __shared__ __align__(16) char dyn[];
    __shared__ float sred[8];
    __shared__ unsigned int s_comb, s_last;

    int t = threadIdx.x, lane = t & 31, wid = t >> 5;

    int blk = blockIdx.x, split = blockIdx.y;
    int a = 0, rem = blk, rl = NT;
    while (rem >= rl) { rem -= rl; a++; rl--; }
    int b2 = a + rem;

    // ---- hoisted cp.async addressing ----
    int lrowg = t >> 3;
    int lv    = (t & 7) * 8;
    uint32_t sA0 = smem_u32(dyn) + (uint32_t)(lrowg * PITCH + lv) * 2;
    uint32_t sB0 = sA0 + SLABB;
    const uint32_t rowStep = 32 * PITCH * 2;
    const __nv_bfloat16* gA0 = g_Yb + (size_t)(split * KSPLIT + lrowg) * D_TOT + a * TILE + lv;
    const __nv_bfloat16* gB0 = g_Yb + (size_t)(split * KSPLIT + lrowg) * D_TOT + b2 * TILE + lv;
    const size_t gRow = (size_t)32 * D_TOT;
    const size_t gChunk = (size_t)CHUNK * D_TOT;

    auto load_chunk = [&](int s, int c) {
        uint32_t so = (uint32_t)(s * 2 * SLABB);
        const __nv_bfloat16* ga = gA0 + c * gChunk;
        const __nv_bfloat16* gb = gB0 + c * gChunk;
        cp16(sA0 + so,           ga);
        cp16(sA0 + so + rowStep, ga + gRow);
        cp16(sB0 + so,           gb);
        cp16(sB0 + so + rowStep, gb + gRow);
    };

    // ---- warp tiling: 2x2 quadrants x 2 k-halves ----
    int wq = wid & 3, kh = wid >> 2;
    int m0 = (wq & 1) * 32;
    int n0 = (wq >> 1) * 32;
    int lrow = (lane & 7) + ((lane >> 4) & 1) * 8;
    int lcol = ((lane >> 3) & 1) * 8;
    uint32_t base = smem_u32(dyn);
    uint32_t aA = base + (uint32_t)((kh * 32 + lrow) * PITCH + m0 + lcol) * 2;
    uint32_t aB = base + SLABB + (uint32_t)((kh * 32 + lrow) * PITCH + n0 + lcol) * 2;
    const uint32_t kStep = 16 * PITCH * 2;

    float acc[2][4][4] = {};

    // prologue: 3 chunks in flight
    load_chunk(0, 0);
    asm volatile("cp.async.commit_group;" ::: "memory");
    load_chunk(1, 1);
    asm volatile("cp.async.commit_group;" ::: "memory");
    load_chunk(2, 2);
    asm volatile("cp.async.commit_group;" ::: "memory");

    int s = 0;
    for (int c = 0; c < NCHUNK_S; c++) {
        asm volatile("cp.async.wait_group 2;" ::: "memory");
        __syncthreads();

        if (c + 3 < NCHUNK_S) {
            int s2 = s + 3; if (s2 >= STAGES) s2 -= STAGES;
            load_chunk(s2, c + 3);
        }
        asm volatile("cp.async.commit_group;" ::: "memory");

        uint32_t so = (uint32_t)(s * 2 * SLABB);
        uint32_t af[2][2][4], bf[2][2][4];
        #pragma unroll
        for (int ks = 0; ks < 2; ks++) {
            uint32_t ko = so + ks * kStep;
            ldsm_x4_t(af[ks][0], aA + ko);
            ldsm_x4_t(af[ks][1], aA + ko + 32);
            ldsm_x4_t(bf[ks][0], aB + ko);
            ldsm_x4_t(bf[ks][1], aB + ko + 32);
        }
        #pragma unroll
        for (int ks = 0; ks < 2; ks++)
            #pragma unroll
            for (int mi = 0; mi < 2; mi++) {
                mma_bf16(acc[mi][0], af[ks][mi], bf[ks][0][0], bf[ks][0][2]);
                mma_bf16(acc[mi][1], af[ks][mi], bf[ks][0][1], bf[ks][0][3]);
                mma_bf16(acc[mi][2], af[ks][mi], bf[ks][1][0], bf[ks][1][2]);
                mma_bf16(acc[mi][3], af[ks][mi], bf[ks][1][1], bf[ks][1][3]);
            }
        if (++s >= STAGES) s -= STAGES;
    }

    // ---- merge k-halves via SMEM, write partial Gram ----
    __syncthreads();
    float4* M4 = (float4*)dyn;
    int tt = wq * 32 + lane;
    if (kh == 1) {
        #pragma unroll
        for (int mi = 0; mi < 2; mi++)
            #pragma unroll
            for (int ni = 0; ni < 4; ni++)
                M4[(mi * 4 + ni) * 128 + tt] =
                    make_float4(acc[mi][ni][0], acc[mi][ni][1],
                                acc[mi][ni][2], acc[mi][ni][3]);
    }
    __syncthreads();
    if (kh == 0) {
        float4* G4 = (float4*)g_G + ((size_t)(split * NTILES + blk)) * 1024;
        #pragma unroll
        for (int mi = 0; mi < 2; mi++)
            #pragma unroll
            for (int ni = 0; ni < 4; ni++) {
                int f = mi * 4 + ni;
                float4 v = M4[f * 128 + tt];
                G4[f * 128 + tt] = make_float4(acc[mi][ni][0] + v.x,
                                               acc[mi][ni][1] + v.y,
                                               acc[mi][ni][2] + v.z,
                                               acc[mi][ni][3] + v.w);
            }
    }

    // ---- decoupled per-tile combine (threadFenceReduction pattern) ----
    __syncthreads();
    if (t == 0) {
        __threadfence();
        s_comb = (atomicAdd(&g_tile_count[blk], 1u) == NSPLIT - 1);
    }
    __syncthreads();
    if (!s_comb) return;

    __threadfence();   // acquire partials written by sibling CTAs
    {
        const float4* G4 = (const float4*)g_G;
        float sum = 0.f;
        #pragma unroll
        for (int f = 0; f < 4; f++) {
            size_t idx = (size_t)blk * 1024 + f * 256 + t;
            float x = 0.f, y = 0.f, z = 0.f, w = 0.f;
            #pragma unroll
            for (int sp = 0; sp < NSPLIT; sp++) {   // fixed order: deterministic
                float4 u = G4[(size_t)sp * NTILES * 1024 + idx];
                x += u.x; y += u.y; z += u.z; w += u.w;
            }
            sum += x * x + y * y + z * z + w * w;
        }
        #pragma unroll
        for (int o = 16; o > 0; o >>= 1)
            sum += __shfl_xor_sync(0xFFFFFFFFu, sum, o);
        if (lane == 0) sred[wid] = sum;
    }
    __syncthreads();
    if (t == 0) {
        float tot = 0.f;
        #pragma unroll
        for (int i = 0; i < 8; i++) tot += sred[i];
        float sp = ((a < 2) != (b2 < 2)) ? -1.f : 1.f;
        float w  = sp * ((a == b2) ? 1.f : 2.f);
        g_part[blk] = w * tot;
        g_tile_count[blk] = 0;     // reset for next graph replay
        __threadfence();
        s_last = (atomicAdd(&g_count, 1u) == NTILES - 1);
    }
    __syncthreads();

    // ---- global finalize by last tile-combiner ----
    if (s_last) {
        __threadfence();
        __shared__ float fs[256];
        fs[t] = (t < NTILES) ? g_part[t] : 0.f;
        __syncthreads();
        #pragma unroll
        for (int o = 128; o > 0; o >>= 1) {
            if (t < o) fs[t] += fs[t + o];
            __syncthreads();
        }
        if (t == 0) {
            out[0] = fs[0] / ((float)N_SAMPLES * (float)(N_SAMPLES - 1));
            g_count = 0;           // reset for next graph replay
        }
    }
}

// ---------------------------------------------------------------------------
extern "C" void kernel_launch(void* const* d_in, const int* in_sizes, int n_in,
                              void* d_out, int out_size) {
    const float* red;
    const float* full;
    if (in_sizes[0] == N_SAMPLES * D_RED) {
        red  = (const float*)d_in[0];
        full = (const float*)d_in[1];
    } else {
        red  = (const float*)d_in[1];
        full = (const float*)d_in[0];
    }

    static int attr_done = 0;
    if (!attr_done) {
        cudaFuncSetAttribute(gram_kernel, cudaFuncAttributeMaxDynamicSharedMemorySize,
                             GSMEM);
        attr_done = 1;
    }

    normalize_kernel<<<N_SAMPLES / 8, 256>>>(red, full);
    gram_kernel<<<dim3(NTILES, NSPLIT), 256, GSMEM>>>((float*)d_out);
}

// round 15
// speedup vs baseline: 1.3347x; 1.0799x over previous
#include <cuda_runtime.h>
#include <cuda_bf16.h>
#include <cstdint>

// ContrastiveCosineLoss via signed feature-Gram SYRK on warp-level bf16 MMA.
// Round 15: kill the LDGSTS issue bottleneck. Normalize writes a blocked
// pre-padded layout (one contiguous 9216B slab per (tile,chunk), identical to
// the gram SMEM layout); gram loads each slab with ONE cp.async.bulk into a
// 3-stage mbarrier pipeline (16 bulk instrs/CTA vs 8192 cp.async).
// Gram config = R8 (64x64 tiles, split-K=4, fused decoupled combine).

#define N_SAMPLES 2048
#define D_RED     128
#define D_TOT     1152                  // 18 * 64
#define TILE      64
#define NT        18
#define NTILES    171
#define NSPLIT    4
#define NCHUNK    32                    // total 64-sample chunks
#define NCHUNK_S  (NCHUNK / NSPLIT)     // 8 chunks per split
#define PITCHB    144                   // bytes per slab row (72 bf16, LDSM-safe)
#define SLABB     (64 * PITCHB)         // 9216 B per (tile,chunk) slab
#define STAGES    3
#define GSMEM     (STAGES * 2 * SLABB)  // 55296 B dynamic smem

__device__ __align__(4096) unsigned char g_Ys[NT * NCHUNK * SLABB]; // blocked bf16
__device__ __align__(4096) float g_G[NSPLIT * NTILES * TILE * TILE];
__device__ float g_part[NTILES];
__device__ unsigned int g_tile_count[NTILES];  // zero-init; self-resetting
__device__ unsigned int g_count;               // zero-init; self-resetting

// ---------------------------------------------------------------------------
__device__ __forceinline__ uint32_t smem_u32(const void* p) {
    uint32_t a;
    asm("{ .reg .u64 t; cvta.to.shared.u64 t, %1; cvt.u32.u64 %0, t; }" : "=r"(a) : "l"(p));
    return a;
}
__device__ __forceinline__ void mbar_init(uint32_t a, uint32_t cnt) {
    asm volatile("mbarrier.init.shared.b64 [%0], %1;" :: "r"(a), "r"(cnt) : "memory");
}
__device__ __forceinline__ void mbar_expect_tx(uint32_t a, uint32_t tx) {
    asm volatile("mbarrier.arrive.expect_tx.shared.b64 _, [%0], %1;"
                 :: "r"(a), "r"(tx) : "memory");
}
__device__ __forceinline__ void mbar_wait(uint32_t a, uint32_t parity) {
    asm volatile(
        "{\n\t.reg .pred P;\n\t"
        "WL_%=:\n\t"
        "mbarrier.try_wait.parity.acquire.cta.shared::cta.b64 P, [%0], %1, 0x989680;\n\t"
        "@!P bra WL_%=;\n\t}"
        :: "r"(a), "r"(parity) : "memory");
}
__device__ __forceinline__ void bulk_g2s(uint32_t sdst, const void* gsrc,
                                         uint32_t bytes, uint32_t mbar) {
    asm volatile(
        "cp.async.bulk.shared::cta.global.mbarrier::complete_tx::bytes "
        "[%0], [%1], %2, [%3];"
        :: "r"(sdst), "l"(gsrc), "r"(bytes), "r"(mbar) : "memory");
}
__device__ __forceinline__ void ldsm_x4_t(uint32_t* r, uint32_t addr) {
    asm volatile("ldmatrix.sync.aligned.m8n8.x4.trans.shared.b16 {%0,%1,%2,%3}, [%4];"
                 : "=r"(r[0]), "=r"(r[1]), "=r"(r[2]), "=r"(r[3]) : "r"(addr));
}
__device__ __forceinline__ void mma_bf16(float* c, const uint32_t* a, uint32_t b0, uint32_t b1) {
    asm volatile(
        "mma.sync.aligned.m16n8k16.row.col.f32.bf16.bf16.f32 "
        "{%0,%1,%2,%3}, {%4,%5,%6,%7}, {%8,%9}, {%0,%1,%2,%3};"
        : "+f"(c[0]), "+f"(c[1]), "+f"(c[2]), "+f"(c[3])
        : "r"(a[0]), "r"(a[1]), "r"(a[2]), "r"(a[3]), "r"(b0), "r"(b1));
}
__device__ __forceinline__ uint2 pack4_bf16(float x, float y, float z, float w) {
    __nv_bfloat162 h0 = __floats2bfloat162_rn(x, y);
    __nv_bfloat162 h1 = __floats2bfloat162_rn(z, w);
    return make_uint2(*(uint32_t*)&h0, *(uint32_t*)&h1);
}

// ---------------------------------------------------------------------------
// Kernel 1: row-normalize -> bf16, written DIRECTLY in the blocked slab
// layout: g_Ys[(tile*32 + chunk)*9216 + sample*144 + feat*2].
// One warp per sample row, MLP 8.
// ---------------------------------------------------------------------------
__global__ void __launch_bounds__(256) normalize_kernel(const float* __restrict__ red,
                                                        const float* __restrict__ full) {
    int t = threadIdx.x, lane = t & 31, wid = t >> 5;
    int row = blockIdx.x * 8 + wid;

    const float4* f4 = (const float4*)(full + (size_t)row * 1024);
    const float4* r4 = (const float4*)(red  + (size_t)row * D_RED);

    float4 fv[8];
    #pragma unroll
    for (int j = 0; j < 8; j++) fv[j] = f4[lane + 32 * j];
    float4 rv = r4[lane];

    float sf = 0.f;
    #pragma unroll
    for (int j = 0; j < 8; j++)
        sf += fv[j].x * fv[j].x + fv[j].y * fv[j].y + fv[j].z * fv[j].z + fv[j].w * fv[j].w;
    float sr = rv.x * rv.x + rv.y * rv.y + rv.z * rv.z + rv.w * rv.w;

    #pragma unroll
    for (int o = 16; o > 0; o >>= 1) {
        sf += __shfl_xor_sync(0xFFFFFFFFu, sf, o);
        sr += __shfl_xor_sync(0xFFFFFFFFu, sr, o);
    }
    float iff = 1.f / fmaxf(sqrtf(sf), 1e-8f);
    float ir  = 1.f / fmaxf(sqrtf(sr), 1e-8f);

    int c = row >> 6, s = row & 63;
    size_t rowOff = (size_t)c * SLABB + (size_t)s * PITCHB + (lane & 15) * 8;
    const size_t tileStride = (size_t)NCHUNK * SLABB;

    {   // reduced block -> tiles 0,1 (feature = lane*4)
        int tile = lane >> 4;
        *(uint2*)(g_Ys + tile * tileStride + rowOff) =
            pack4_bf16(rv.x * ir, rv.y * ir, rv.z * ir, rv.w * ir);
    }
    #pragma unroll
    for (int j = 0; j < 8; j++) {   // full block -> tiles 2..17
        int tile = 2 + j * 2 + (lane >> 4);
        *(uint2*)(g_Ys + tile * tileStride + rowOff) =
            pack4_bf16(fv[j].x * iff, fv[j].y * iff, fv[j].z * iff, fv[j].w * iff);
    }
}

// ---------------------------------------------------------------------------
// Kernel 2: bf16 warp-MMA partial SYRK (split-K=4), cp.async.bulk + mbarrier
// pipeline, decoupled per-tile combine + global finalize.
// grid = (NTILES, NSPLIT), 256 threads, 8 warps = 2x2 quadrants x 2 k-halves.
// ---------------------------------------------------------------------------
__global__ void __launch_bounds__(256, 3) gram_kernel(float* __restrict__ out) {
    extern __shared__ __align__(16) char dyn[];
    __shared__ __align__(8) unsigned long long s_mbar[STAGES];
    __shared__ float sred[8];
    __shared__ unsigned int s_comb, s_last;

    int t = threadIdx.x, lane = t & 31, wid = t >> 5;

    int blk = blockIdx.x, split = blockIdx.y;
    int a = 0, rem = blk, rl = NT;
    while (rem >= rl) { rem -= rl; a++; rl--; }
    int b2 = a + rem;

    const uint32_t sbase = smem_u32(dyn);
    const unsigned char* gA = g_Ys + ((size_t)a  * NCHUNK + split * NCHUNK_S) * SLABB;
    const unsigned char* gB = g_Ys + ((size_t)b2 * NCHUNK + split * NCHUNK_S) * SLABB;

    uint32_t mb[STAGES];
    #pragma unroll
    for (int s = 0; s < STAGES; s++) mb[s] = smem_u32(&s_mbar[s]);

    if (t == 0) {
        #pragma unroll
        for (int s = 0; s < STAGES; s++) mbar_init(mb[s], 1);
    }
    __syncthreads();

    auto issue = [&](int s, int c) {   // t==0 only
        uint32_t dst = sbase + (uint32_t)(s * 2 * SLABB);
        mbar_expect_tx(mb[s], 2 * SLABB);
        bulk_g2s(dst,         gA + (size_t)c * SLABB, SLABB, mb[s]);
        bulk_g2s(dst + SLABB, gB + (size_t)c * SLABB, SLABB, mb[s]);
    };

    if (t == 0) { issue(0, 0); issue(1, 1); }

    // ---- warp tiling: 2x2 quadrants x 2 k-halves (R8 addressing) ----
    int wq = wid & 3, kh = wid >> 2;
    int m0 = (wq & 1) * 32;
    int n0 = (wq >> 1) * 32;
    int lrow = (lane & 7) + ((lane >> 4) & 1) * 8;
    int lcol = ((lane >> 3) & 1) * 8;
    const uint32_t offA = (uint32_t)((kh * 32 + lrow) * PITCHB + (m0 + lcol) * 2);
    const uint32_t offB = (uint32_t)(SLABB + (kh * 32 + lrow) * PITCHB + (n0 + lcol) * 2);
    const uint32_t kStep = 16 * PITCHB;

    float acc[2][4][4] = {};

    for (int c = 0; c < NCHUNK_S; c++) {
        int s = c;  while (s >= STAGES) s -= STAGES;      // c % 3
        int parity = (c / STAGES) & 1;
        mbar_wait(mb[s], parity);
        __syncthreads();      // all warps done with stage (c+2)%3 before refill

        if (t == 0 && c + 2 < NCHUNK_S) {
            int s2 = s + 2; if (s2 >= STAGES) s2 -= STAGES;
            issue(s2, c + 2);
        }

        uint32_t so = sbase + (uint32_t)(s * 2 * SLABB);
        uint32_t aA = so + offA, aB = so + offB;
        uint32_t af[2][2][4], bf[2][2][4];
        #pragma unroll
        for (int ks = 0; ks < 2; ks++) {
            uint32_t ko = ks * kStep;
            ldsm_x4_t(af[ks][0], aA + ko);
            ldsm_x4_t(af[ks][1], aA + ko + 32);
            ldsm_x4_t(bf[ks][0], aB + ko);
            ldsm_x4_t(bf[ks][1], aB + ko + 32);
        }
        #pragma unroll
        for (int ks = 0; ks < 2; ks++)
            #pragma unroll
            for (int mi = 0; mi < 2; mi++) {
                mma_bf16(acc[mi][0], af[ks][mi], bf[ks][0][0], bf[ks][0][2]);
                mma_bf16(acc[mi][1], af[ks][mi], bf[ks][0][1], bf[ks][0][3]);
                mma_bf16(acc[mi][2], af[ks][mi], bf[ks][1][0], bf[ks][1][2]);
                mma_bf16(acc[mi][3], af[ks][mi], bf[ks][1][1], bf[ks][1][3]);
            }
    }

    // ---- merge k-halves via SMEM, write partial Gram ----
    __syncthreads();
    float4* M4 = (float4*)dyn;
    int tt = wq * 32 + lane;
    if (kh == 1) {
        #pragma unroll
        for (int mi = 0; mi < 2; mi++)
            #pragma unroll
            for (int ni = 0; ni < 4; ni++)
                M4[(mi * 4 + ni) * 128 + tt] =
                    make_float4(acc[mi][ni][0], acc[mi][ni][1],
                                acc[mi][ni][2], acc[mi][ni][3]);
    }
    __syncthreads();
    if (kh == 0) {
        float4* G4 = (float4*)g_G + ((size_t)(split * NTILES + blk)) * 1024;
        #pragma unroll
        for (int mi = 0; mi < 2; mi++)
            #pragma unroll
            for (int ni = 0; ni < 4; ni++) {
                int f = mi * 4 + ni;
                float4 v = M4[f * 128 + tt];
                G4[f * 128 + tt] = make_float4(acc[mi][ni][0] + v.x,
                                               acc[mi][ni][1] + v.y,
                                               acc[mi][ni][2] + v.z,
                                               acc[mi][ni][3] + v.w);
            }
    }

    // ---- decoupled per-tile combine (threadFenceReduction pattern) ----
    __syncthreads();
    if (t == 0) {
        __threadfence();
        s_comb = (atomicAdd(&g_tile_count[blk], 1u) == NSPLIT - 1);
    }
    __syncthreads();
    if (!s_comb) return;

    __threadfence();   // acquire partials written by sibling CTAs
    {
        const float4* G4 = (const float4*)g_G;
        float sum = 0.f;
        #pragma unroll
        for (int f = 0; f < 4; f++) {
            size_t idx = (size_t)blk * 1024 + f * 256 + t;
            float x = 0.f, y = 0.f, z = 0.f, w = 0.f;
            #pragma unroll
            for (int sp = 0; sp < NSPLIT; sp++) {   // fixed order: deterministic
                float4 u = G4[(size_t)sp * NTILES * 1024 + idx];
                x += u.x; y += u.y; z += u.z; w += u.w;
            }
            sum += x * x + y * y + z * z + w * w;
        }
        #pragma unroll
        for (int o = 16; o > 0; o >>= 1)
            sum += __shfl_xor_sync(0xFFFFFFFFu, sum, o);
        if (lane == 0) sred[wid] = sum;
    }
    __syncthreads();
    if (t == 0) {
        float tot = 0.f;
        #pragma unroll
        for (int i = 0; i < 8; i++) tot += sred[i];
        float sp = ((a < 2) != (b2 < 2)) ? -1.f : 1.f;
        float w  = sp * ((a == b2) ? 1.f : 2.f);
        g_part[blk] = w * tot;
        g_tile_count[blk] = 0;     // reset for next graph replay
        __threadfence();
        s_last = (atomicAdd(&g_count, 1u) == NTILES - 1);
    }
    __syncthreads();

    // ---- global finalize by last tile-combiner ----
    if (s_last) {
        __threadfence();
        __shared__ float fs[256];
        fs[t] = (t < NTILES) ? g_part[t] : 0.f;
        __syncthreads();
        #pragma unroll
        for (int o = 128; o > 0; o >>= 1) {
            if (t < o) fs[t] += fs[t + o];
            __syncthreads();
        }
        if (t == 0) {
            out[0] = fs[0] / ((float)N_SAMPLES * (float)(N_SAMPLES - 1));
            g_count = 0;           // reset for next graph replay
        }
    }
}

// ---------------------------------------------------------------------------
extern "C" void kernel_launch(void* const* d_in, const int* in_sizes, int n_in,
                              void* d_out, int out_size) {
    const float* red;
    const float* full;
    if (in_sizes[0] == N_SAMPLES * D_RED) {
        red  = (const float*)d_in[0];
        full = (const float*)d_in[1];
    } else {
        red  = (const float*)d_in[1];
        full = (const float*)d_in[0];
    }

    static int attr_done = 0;
    if (!attr_done) {
        cudaFuncSetAttribute(gram_kernel, cudaFuncAttributeMaxDynamicSharedMemorySize,
                             GSMEM);
        attr_done = 1;
    }

    normalize_kernel<<<N_SAMPLES / 8, 256>>>(red, full);
    gram_kernel<<<dim3(NTILES, NSPLIT), 256, GSMEM>>>((float*)d_out);
}